// round 17
// baseline (speedup 1.0000x reference)
#include <cuda_runtime.h>
#include <cuda_fp16.h>

#define NN 50000
#define NE 800000
#define D 128
#define OUTW4 160        // 640 floats / 4 per output row
#define DEG_BLOCKS 1563  // ceil((NE/2) / 256)
#define CM_BLOCKS 98     // 784 warps x 64 rows covers 50000

// ---- scratch (__device__ globals; no allocations allowed) ----
__device__ unsigned long long g_pack[NN];       // (count << 40) | fixpoint32(sum w)
__device__ float              g_deg[NN];        // dinv
__device__ int                g_alloc;          // bump allocator
__device__ int                g_rank[NE];       // per-edge rank within its col
__device__ uint4              g_seg[NN];        // {start, cnt, dinv_bits, 0}
__device__ unsigned long long g_csr[NE];        // packed (w_bits << 32) | (row * 32)
__device__ float              g_gsum[D];        // global feature sum
__device__ __align__(16) __half g_m0[NN * D];   // fp16 mirror ping
__device__ __align__(16) __half g_m1[NN * D];   // fp16 mirror pong

// ---------------------------------------------------------------------------
__global__ void zero_kernel() {
    int i = blockIdx.x * blockDim.x + threadIdx.x;
    if (i < NN) g_pack[i] = 0ull;
    if (i < D)  g_gsum[i] = 0.0f;
    if (i == 0) g_alloc = 0;
}

// FUSED: blocks [0, DEG_BLOCKS) do edge-degree atomics (2 edges/thread);
// blocks [DEG_BLOCKS, ...) do copy_mean (independent, overlapped).
__global__ void deg_copy_kernel(const int* __restrict__ ei,
                                const float* __restrict__ ew,
                                const float* __restrict__ x,
                                float* __restrict__ out) {
    if (blockIdx.x < DEG_BLOCKS) {
        int t = blockIdx.x * 256 + threadIdx.x;
        int e0 = t * 2;
        if (e0 >= NE) return;
        int2   c2 = *(const int2*)&ei[NE + e0];
        float2 w2 = *(const float2*)&ew[e0];
        {
            unsigned long long v =
                (1ull << 40) | (unsigned long long)((double)w2.x * 4294967296.0);
            unsigned long long old = atomicAdd(&g_pack[c2.x], v);
            g_rank[e0] = (int)(old >> 40);
        }
        {
            unsigned long long v =
                (1ull << 40) | (unsigned long long)((double)w2.y * 4294967296.0);
            unsigned long long old = atomicAdd(&g_pack[c2.y], v);
            g_rank[e0 + 1] = (int)(old >> 40);
        }
    } else {
        int lane = threadIdx.x & 31;
        int wrp  = (blockIdx.x - DEG_BLOCKS) * 8 + (threadIdx.x >> 5);
        int r0 = wrp * 64;
        if (r0 >= NN) return;
        int r1 = min(r0 + 64, NN);
        const float4* x4 = (const float4*)x;
        float4* out4 = (float4*)out;
        uint2* m0 = (uint2*)g_m0;
        float4 s = make_float4(0.f, 0.f, 0.f, 0.f);
        for (int r = r0; r < r1; r++) {
            float4 v = x4[r * 32 + lane];
            __stcs(&out4[(long long)r * OUTW4 + lane], v);  // write-once: stream
            __half2 h0 = __floats2half2_rn(v.x, v.y);
            __half2 h1 = __floats2half2_rn(v.z, v.w);
            uint2 mv;
            mv.x = *(unsigned int*)&h0;
            mv.y = *(unsigned int*)&h1;
            m0[r * 32 + lane] = mv;                          // cached: hop1 reads
            s.x += v.x; s.y += v.y; s.z += v.z; s.w += v.w;
        }
        atomicAdd(&g_gsum[lane * 4 + 0], s.x);
        atomicAdd(&g_gsum[lane * 4 + 1], s.y);
        atomicAdd(&g_gsum[lane * 4 + 2], s.z);
        atomicAdd(&g_gsum[lane * 4 + 3], s.w);
    }
}

// dinv + segment bump-alloc; seg carries {start, cnt, dinv} in one 16B word
__global__ void alloc_kernel() {
    int i = blockIdx.x * 256 + threadIdx.x;
    int lane = threadIdx.x & 31;
    int cnt = 0;
    float dinv = 0.0f;
    if (i < NN) {
        unsigned long long p = g_pack[i];
        cnt = (int)(p >> 40);
        double d = (double)(p & ((1ull << 40) - 1ull)) * (1.0 / 4294967296.0);
        dinv = (d > 0.0) ? rsqrtf((float)d) : 0.0f;
        g_deg[i] = dinv;
    }
    int iv = cnt;
    #pragma unroll
    for (int s = 1; s < 32; s <<= 1) {
        int t = __shfl_up_sync(0xffffffffu, iv, s);
        if (lane >= s) iv += t;
    }
    int base = 0;
    if (lane == 31) base = atomicAdd(&g_alloc, iv);
    base = __shfl_sync(0xffffffffu, base, 31);
    int start = base + iv - cnt;
    if (i < NN)
        g_seg[i] = make_uint4((unsigned int)start, (unsigned int)cnt,
                              __float_as_uint(dinv), 0u);
}

// scatter: stores FULL normalized weight.
__global__ void scatter_kernel(const int* __restrict__ ei,
                               const float* __restrict__ ew) {
    int e = blockIdx.x * blockDim.x + threadIdx.x;
    if (e >= NE) return;
    int row = ei[e];
    int col = ei[NE + e];
    uint4 s4 = g_seg[col];                           // one 16B random read
    float w = g_deg[row] * ew[e] * __uint_as_float(s4.z);
    int pos = (int)s4.x + g_rank[e];
    g_csr[pos] = ((unsigned long long)__float_as_uint(w) << 32) |
                 (unsigned int)(row * 32);           // row offset in uint2 units
}

// half-warp-per-edge gather: lane loads uint4 (16B), 16 lanes cover one row,
// warp processes 2 edges per iteration. acc[8] per lane; halves combined by shfl.
// which = 0: in=m0, mir=m1 | 1: in=m1, mir=m0 | 2: in=m0, final (+ mean slab)
__global__ void hop_kernel(float* __restrict__ out, int out_off4, int which) {
    int lane = threadIdx.x & 31;
    int h    = lane >> 4;          // half-warp id: which edge of the pair
    int s    = lane & 15;          // sublane: which 16B chunk of the row
    int node = blockIdx.x * 8 + (threadIdx.x >> 5);
    if (node >= NN) return;
    const uint4* __restrict__ in4 =
        (which == 1) ? (const uint4*)g_m1 : (const uint4*)g_m0;
    uint4 seg = g_seg[node];
    int start = (int)seg.x;
    int cnt   = (int)seg.y;
    float acc0 = 0.f, acc1 = 0.f, acc2 = 0.f, acc3 = 0.f;
    float acc4 = 0.f, acc5 = 0.f, acc6 = 0.f, acc7 = 0.f;

    int pair_end = start + (cnt & ~1);
    int e = start;
    for (; e + 8 <= pair_end; e += 8) {            // 4 pairs = 8 edges in flight
        unsigned long long p[4];
        uint4 v[4];
        #pragma unroll
        for (int k = 0; k < 4; k++) p[k] = __ldg(&g_csr[e + 2 * k + h]);
        #pragma unroll
        for (int k = 0; k < 4; k++)
            v[k] = __ldg(&in4[((int)(p[k] & 0xffffffffu) >> 1) + s]);
        #pragma unroll
        for (int k = 0; k < 4; k++) {
            float w = __uint_as_float((unsigned int)(p[k] >> 32));
            float2 f0 = __half22float2(*(__half2*)&v[k].x);
            float2 f1 = __half22float2(*(__half2*)&v[k].y);
            float2 f2 = __half22float2(*(__half2*)&v[k].z);
            float2 f3 = __half22float2(*(__half2*)&v[k].w);
            acc0 += w * f0.x; acc1 += w * f0.y; acc2 += w * f1.x; acc3 += w * f1.y;
            acc4 += w * f2.x; acc5 += w * f2.y; acc6 += w * f3.x; acc7 += w * f3.y;
        }
    }
    for (; e < pair_end; e += 2) {                 // leftover pairs
        unsigned long long p = __ldg(&g_csr[e + h]);
        uint4 v = __ldg(&in4[((int)(p & 0xffffffffu) >> 1) + s]);
        float w = __uint_as_float((unsigned int)(p >> 32));
        float2 f0 = __half22float2(*(__half2*)&v.x);
        float2 f1 = __half22float2(*(__half2*)&v.y);
        float2 f2 = __half22float2(*(__half2*)&v.z);
        float2 f3 = __half22float2(*(__half2*)&v.w);
        acc0 += w * f0.x; acc1 += w * f0.y; acc2 += w * f1.x; acc3 += w * f1.y;
        acc4 += w * f2.x; acc5 += w * f2.y; acc6 += w * f3.x; acc7 += w * f3.y;
    }
    if (cnt & 1) {                                 // odd tail: half 1 contributes 0
        unsigned long long p = __ldg(&g_csr[start + cnt - 1]);
        uint4 v = __ldg(&in4[((int)(p & 0xffffffffu) >> 1) + s]);
        float w = (h == 0) ? __uint_as_float((unsigned int)(p >> 32)) : 0.0f;
        float2 f0 = __half22float2(*(__half2*)&v.x);
        float2 f1 = __half22float2(*(__half2*)&v.y);
        float2 f2 = __half22float2(*(__half2*)&v.z);
        float2 f3 = __half22float2(*(__half2*)&v.w);
        acc0 += w * f0.x; acc1 += w * f0.y; acc2 += w * f1.x; acc3 += w * f1.y;
        acc4 += w * f2.x; acc5 += w * f2.y; acc6 += w * f3.x; acc7 += w * f3.y;
    }

    // combine the two half-warp partial sums
    acc0 += __shfl_xor_sync(0xffffffffu, acc0, 16);
    acc1 += __shfl_xor_sync(0xffffffffu, acc1, 16);
    acc2 += __shfl_xor_sync(0xffffffffu, acc2, 16);
    acc3 += __shfl_xor_sync(0xffffffffu, acc3, 16);
    acc4 += __shfl_xor_sync(0xffffffffu, acc4, 16);
    acc5 += __shfl_xor_sync(0xffffffffu, acc5, 16);
    acc6 += __shfl_xor_sync(0xffffffffu, acc6, 16);
    acc7 += __shfl_xor_sync(0xffffffffu, acc7, 16);

    // lane (h,s) owns features 8s+4h .. 8s+4h+3  -> float4 index 2s+h in the slab
    float o0 = (h == 0) ? acc0 : acc4;
    float o1 = (h == 0) ? acc1 : acc5;
    float o2 = (h == 0) ? acc2 : acc6;
    float o3 = (h == 0) ? acc3 : acc7;
    float4 xo = make_float4(o0, o1, o2, o3);
    __stcs(&((float4*)out)[(long long)node * OUTW4 + out_off4 + 2 * s + h], xo);

    if (which != 2) {
        uint2* mir2 = (which == 0) ? (uint2*)g_m1 : (uint2*)g_m0;
        __half2 h0 = __floats2half2_rn(o0, o1);
        __half2 h1 = __floats2half2_rn(o2, o3);
        uint2 mv;
        mv.x = *(unsigned int*)&h0;
        mv.y = *(unsigned int*)&h1;
        mir2[node * 32 + 2 * s + h] = mv;            // cached: read next hop
    } else {
        const float inv = 1.0f / (float)NN;
        float4 gs = ((const float4*)g_gsum)[2 * s + h];
        float4 g = make_float4(gs.x * inv, gs.y * inv, gs.z * inv, gs.w * inv);
        __stcs(&((float4*)out)[(long long)node * OUTW4 + 128 + 2 * s + h], g);
    }
}

// ---------------------------------------------------------------------------
extern "C" void kernel_launch(void* const* d_in, const int* in_sizes, int n_in,
                              void* d_out, int out_size) {
    const float* x  = (const float*)d_in[0];
    const int*   ei = (const int*)d_in[1];
    const float* ew = (const float*)d_in[2];
    float* out = (float*)d_out;

    zero_kernel<<<(NN + 255) / 256, 256>>>();
    deg_copy_kernel<<<DEG_BLOCKS + CM_BLOCKS, 256>>>(ei, ew, x, out);
    alloc_kernel<<<(NN + 255) / 256, 256>>>();
    scatter_kernel<<<(NE + 255) / 256, 256>>>(ei, ew);

    hop_kernel<<<(NN + 7) / 8, 256>>>(out, 32, 0);  // m0 -> slab1, mirror m1
    hop_kernel<<<(NN + 7) / 8, 256>>>(out, 64, 1);  // m1 -> slab2, mirror m0
    hop_kernel<<<(NN + 7) / 8, 256>>>(out, 96, 2);  // m0 -> slab3, + mean slab
}